// round 2
// baseline (speedup 1.0000x reference)
#include <cuda_runtime.h>
#include <cstdint>

#define N_DIM 8192
#define K_DIM 4096
#define M_DIM 4096

// Scratch (device globals: no allocation allowed in kernel_launch)
__device__ int8_t g_qx[(size_t)N_DIM * K_DIM];   // quantized x  [N, K]
__device__ int8_t g_qw[(size_t)M_DIM * K_DIM];   // quantized w  [M, K]
__device__ unsigned int g_amax_bits[2];          // [0]=amax(x), [1]=amax(w) as float bits

// ---------------------------------------------------------------------------
__global__ void init_kernel() {
    g_amax_bits[0] = 0u;
    g_amax_bits[1] = 0u;
}

// amax reduction (non-negative floats compare correctly as uint bits)
__global__ void amax_kernel(const float* __restrict__ in, long long n4, int slot) {
    float m = 0.0f;
    long long i0 = (long long)blockIdx.x * blockDim.x + threadIdx.x;
    long long stride = (long long)gridDim.x * blockDim.x;
    const float4* in4 = (const float4*)in;
    for (long long i = i0; i < n4; i += stride) {
        float4 v = in4[i];
        m = fmaxf(m, fmaxf(fmaxf(fabsf(v.x), fabsf(v.y)),
                           fmaxf(fabsf(v.z), fabsf(v.w))));
    }
#pragma unroll
    for (int o = 16; o; o >>= 1) m = fmaxf(m, __shfl_xor_sync(0xffffffffu, m, o));
    __shared__ float sm[32];
    int lane = threadIdx.x & 31, wid = threadIdx.x >> 5;
    if (lane == 0) sm[wid] = m;
    __syncthreads();
    if (wid == 0) {
        m = (lane < (int)(blockDim.x >> 5)) ? sm[lane] : 0.0f;
#pragma unroll
        for (int o = 16; o; o >>= 1) m = fmaxf(m, __shfl_xor_sync(0xffffffffu, m, o));
        if (lane == 0) atomicMax(&g_amax_bits[slot], __float_as_uint(m));
    }
}

// quantize: round-to-nearest-even (matches jnp.round), clip to [-127, 127]
__global__ void quant_kernel(const float* __restrict__ in, int8_t* __restrict__ out,
                             long long n4, int slot) {
    float amax = __uint_as_float(g_amax_bits[slot]);
    float scale = 127.0f / amax;
    long long i0 = (long long)blockIdx.x * blockDim.x + threadIdx.x;
    long long stride = (long long)gridDim.x * blockDim.x;
    const float4* in4 = (const float4*)in;
    char4* out4 = (char4*)out;
    for (long long i = i0; i < n4; i += stride) {
        float4 v = in4[i];
        char4 q;
        q.x = (signed char)__float2int_rn(fminf(fmaxf(v.x * scale, -127.0f), 127.0f));
        q.y = (signed char)__float2int_rn(fminf(fmaxf(v.y * scale, -127.0f), 127.0f));
        q.z = (signed char)__float2int_rn(fminf(fmaxf(v.z * scale, -127.0f), 127.0f));
        q.w = (signed char)__float2int_rn(fminf(fmaxf(v.w * scale, -127.0f), 127.0f));
        out4[i] = q;
    }
}

// ---------------------------------------------------------------------------
// int8 GEMM: out[N, M] = (qx [N,K]) * (qw [M,K])^T  (int32 acc), then
// out = acc * dequant + bias.
// Tile: 128x128 output, K-chunk 64 bytes (16 int32 words). 256 threads,
// thread computes 8x8 outputs: rows ty*4+{0..3} and 64+ty*4+{0..3},
// cols tx*4+{0..3} and 64+tx*4+{0..3}. Smem stored transposed
// [kword][row] with row-stride 132 words for conflict-free int4 loads.
#define SROW 132

__global__ __launch_bounds__(256, 2)
void gemm_dp4a_kernel(const int8_t* __restrict__ qx, const int8_t* __restrict__ qw,
                      const float* __restrict__ bias, float* __restrict__ out) {
    __shared__ int As[16 * SROW];  // A tile transposed: As[w*SROW + r]
    __shared__ int Bs[16 * SROW];

    const int tid = threadIdx.x;
    const int tx = tid & 15;   // 0..15  (cols)
    const int ty = tid >> 4;   // 0..15  (rows)

    const int row0 = blockIdx.y * 128;  // N tile base
    const int col0 = blockIdx.x * 128;  // M tile base

    int acc[8][8];
#pragma unroll
    for (int i = 0; i < 8; ++i)
#pragma unroll
        for (int j = 0; j < 8; ++j) acc[i][j] = 0;

    // loader mapping: element e -> row r = e>>2, quad q4 = e&3 (16 bytes each)
    const int rA = tid >> 2;        // e = tid
    const int qA = tid & 3;
    const int rB = (tid + 256) >> 2;  // e = tid + 256
    const int qB = (tid + 256) & 3;

    const size_t strideK = K_DIM;

    for (int kt = 0; kt < K_DIM / 64; ++kt) {
        const int kbase = kt * 64;

        // global -> regs (uint4 = 16 int8)
        uint4 a_v0 = *(const uint4*)(qx + (size_t)(row0 + rA) * strideK + kbase + qA * 16);
        uint4 a_v1 = *(const uint4*)(qx + (size_t)(row0 + rB) * strideK + kbase + qB * 16);
        uint4 b_v0 = *(const uint4*)(qw + (size_t)(col0 + rA) * strideK + kbase + qA * 16);
        uint4 b_v1 = *(const uint4*)(qw + (size_t)(col0 + rB) * strideK + kbase + qB * 16);

        __syncthreads();  // previous compute done before overwriting smem

        // transpose into smem: word w of row r -> [w][r]
        {
            int wb = qA * 4;
            As[(wb + 0) * SROW + rA] = a_v0.x;
            As[(wb + 1) * SROW + rA] = a_v0.y;
            As[(wb + 2) * SROW + rA] = a_v0.z;
            As[(wb + 3) * SROW + rA] = a_v0.w;
            Bs[(wb + 0) * SROW + rA] = b_v0.x;
            Bs[(wb + 1) * SROW + rA] = b_v0.y;
            Bs[(wb + 2) * SROW + rA] = b_v0.z;
            Bs[(wb + 3) * SROW + rA] = b_v0.w;
        }
        {
            int wb = qB * 4;
            As[(wb + 0) * SROW + rB] = a_v1.x;
            As[(wb + 1) * SROW + rB] = a_v1.y;
            As[(wb + 2) * SROW + rB] = a_v1.z;
            As[(wb + 3) * SROW + rB] = a_v1.w;
            Bs[(wb + 0) * SROW + rB] = b_v1.x;
            Bs[(wb + 1) * SROW + rB] = b_v1.y;
            Bs[(wb + 2) * SROW + rB] = b_v1.z;
            Bs[(wb + 3) * SROW + rB] = b_v1.w;
        }
        __syncthreads();

        const int4* As4 = (const int4*)As;  // SROW/4 = 33 int4 per k-word row
        const int4* Bs4 = (const int4*)Bs;

#pragma unroll 4
        for (int kk = 0; kk < 16; ++kk) {
            int4 a0 = As4[kk * 33 + ty];
            int4 a1 = As4[kk * 33 + 16 + ty];
            int4 b0 = Bs4[kk * 33 + tx];
            int4 b1 = Bs4[kk * 33 + 16 + tx];
            int a[8] = {a0.x, a0.y, a0.z, a0.w, a1.x, a1.y, a1.z, a1.w};
            int b[8] = {b0.x, b0.y, b0.z, b0.w, b1.x, b1.y, b1.z, b1.w};
#pragma unroll
            for (int i = 0; i < 8; ++i)
#pragma unroll
                for (int j = 0; j < 8; ++j)
                    acc[i][j] = __dp4a(a[i], b[j], acc[i][j]);
        }
    }

    // epilogue: dequant + bias
    const float dq = (__uint_as_float(g_amax_bits[0]) * __uint_as_float(g_amax_bits[1]))
                     / (127.0f * 127.0f);
#pragma unroll
    for (int i = 0; i < 8; ++i) {
        int row = row0 + ty * 4 + (i & 3) + (i >> 2) * 64;
#pragma unroll
        for (int jg = 0; jg < 2; ++jg) {
            int col = col0 + tx * 4 + jg * 64;
            float4 bv = *(const float4*)(bias + col);
            float4 o;
            o.x = (float)acc[i][jg * 4 + 0] * dq + bv.x;
            o.y = (float)acc[i][jg * 4 + 1] * dq + bv.y;
            o.z = (float)acc[i][jg * 4 + 2] * dq + bv.z;
            o.w = (float)acc[i][jg * 4 + 3] * dq + bv.w;
            *(float4*)(out + (size_t)row * M_DIM + col) = o;
        }
    }
}

// ---------------------------------------------------------------------------
extern "C" void kernel_launch(void* const* d_in, const int* in_sizes, int n_in,
                              void* d_out, int out_size) {
    const float* x = (const float*)d_in[0];      // [N, K]
    const float* w = (const float*)d_in[1];      // [M, K]
    const float* bias = (const float*)d_in[2];   // [M]
    float* out = (float*)d_out;                  // [N, M]

    int8_t* qx;
    int8_t* qw;
    cudaGetSymbolAddress((void**)&qx, g_qx);
    cudaGetSymbolAddress((void**)&qw, g_qw);

    const long long nx4 = (long long)N_DIM * K_DIM / 4;
    const long long nw4 = (long long)M_DIM * K_DIM / 4;

    init_kernel<<<1, 32>>>();
    amax_kernel<<<1024, 256>>>(x, nx4, 0);
    amax_kernel<<<1024, 256>>>(w, nw4, 1);
    quant_kernel<<<1024, 256>>>(x, qx, nx4, 0);
    quant_kernel<<<1024, 256>>>(w, qw, nw4, 1);

    dim3 grid(M_DIM / 128, N_DIM / 128);
    gemm_dp4a_kernel<<<grid, 256>>>(qx, qw, bias, out);
}

// round 7
// speedup vs baseline: 1.0680x; 1.0680x over previous
#include <cuda_runtime.h>
#include <cstdint>

#define N_DIM 8192
#define K_DIM 4096
#define M_DIM 4096

#define BM 128
#define BN 128
#define BK 64
#define STAGES 3
#define K_TILES (K_DIM / BK)   // 64
#define THREADS 256

// Scratch (device globals: no allocation allowed)
__device__ int8_t g_qx[(size_t)N_DIM * K_DIM];
__device__ int8_t g_qw[(size_t)M_DIM * K_DIM];
__device__ unsigned int g_amax_bits[2];

// ---------------------------------------------------------------- helpers
__device__ __forceinline__ uint32_t smem_u32(const void* p) {
    uint32_t a;
    asm("{ .reg .u64 t; cvta.to.shared.u64 t, %1; cvt.u32.u64 %0, t; }" : "=r"(a) : "l"(p));
    return a;
}
// swizzle for 64-byte-row tiles: XOR 16B-chunk bits [4:6) with ((row>>1)&3)
// (row = off>>6, so bits [7:9) of off). Makes each 8-row ldmatrix phase hit
// 8 distinct (bank-half, chunk) combos -> conflict-free.
__device__ __forceinline__ uint32_t swz(uint32_t off) {
    return off ^ ((off >> 3) & 0x30);
}
__device__ __forceinline__ void cp16(uint32_t dst, const void* src) {
    asm volatile("cp.async.cg.shared.global [%0], [%1], 16;" :: "r"(dst), "l"(src));
}
#define CP_COMMIT() asm volatile("cp.async.commit_group;" ::: "memory")

__device__ __forceinline__ void ldmx4(uint32_t* r, uint32_t addr) {
    asm volatile("ldmatrix.sync.aligned.m8n8.x4.shared.b16 {%0,%1,%2,%3}, [%4];"
                 : "=r"(r[0]), "=r"(r[1]), "=r"(r[2]), "=r"(r[3]) : "r"(addr));
}
__device__ __forceinline__ void imma(int* c, const uint32_t* a, uint32_t b0, uint32_t b1) {
    asm volatile(
        "mma.sync.aligned.m16n8k32.row.col.s32.s8.s8.s32 "
        "{%0,%1,%2,%3}, {%4,%5,%6,%7}, {%8,%9}, {%0,%1,%2,%3};"
        : "+r"(c[0]), "+r"(c[1]), "+r"(c[2]), "+r"(c[3])
        : "r"(a[0]), "r"(a[1]), "r"(a[2]), "r"(a[3]), "r"(b0), "r"(b1));
}

// ---------------------------------------------------------------- preproc
__global__ void init_kernel() { g_amax_bits[0] = 0u; g_amax_bits[1] = 0u; }

__global__ void amax_kernel(const float* __restrict__ in, long long n4, int slot) {
    float m = 0.0f;
    long long i0 = (long long)blockIdx.x * blockDim.x + threadIdx.x;
    long long stride = (long long)gridDim.x * blockDim.x;
    const float4* in4 = (const float4*)in;
    for (long long i = i0; i < n4; i += stride) {
        float4 v = in4[i];
        m = fmaxf(m, fmaxf(fmaxf(fabsf(v.x), fabsf(v.y)),
                           fmaxf(fabsf(v.z), fabsf(v.w))));
    }
#pragma unroll
    for (int o = 16; o; o >>= 1) m = fmaxf(m, __shfl_xor_sync(0xffffffffu, m, o));
    __shared__ float sm[32];
    int lane = threadIdx.x & 31, wid = threadIdx.x >> 5;
    if (lane == 0) sm[wid] = m;
    __syncthreads();
    if (wid == 0) {
        m = (lane < (int)(blockDim.x >> 5)) ? sm[lane] : 0.0f;
#pragma unroll
        for (int o = 16; o; o >>= 1) m = fmaxf(m, __shfl_xor_sync(0xffffffffu, m, o));
        if (lane == 0) atomicMax(&g_amax_bits[slot], __float_as_uint(m));
    }
}

__global__ void quant_kernel(const float* __restrict__ in, int8_t* __restrict__ out,
                             long long n4, int slot) {
    float amax = __uint_as_float(g_amax_bits[slot]);
    float scale = 127.0f / amax;
    long long i0 = (long long)blockIdx.x * blockDim.x + threadIdx.x;
    long long stride = (long long)gridDim.x * blockDim.x;
    const float4* in4 = (const float4*)in;
    char4* out4 = (char4*)out;
    for (long long i = i0; i < n4; i += stride) {
        float4 v = in4[i];
        char4 q;
        q.x = (signed char)__float2int_rn(fminf(fmaxf(v.x * scale, -127.0f), 127.0f));
        q.y = (signed char)__float2int_rn(fminf(fmaxf(v.y * scale, -127.0f), 127.0f));
        q.z = (signed char)__float2int_rn(fminf(fmaxf(v.z * scale, -127.0f), 127.0f));
        q.w = (signed char)__float2int_rn(fminf(fmaxf(v.w * scale, -127.0f), 127.0f));
        out4[i] = q;
    }
}

// ---------------------------------------------------------------- IMMA GEMM
// out[N_DIM, M_DIM] = qx[N,K] * qw[M,K]^T (s32 acc) * dq + bias.
// Block 128x128, BK=64. 8 warps: wM = wid&3 (M rows), wN = wid>>2 (out cols).
// Warp tile 32(M) x 64(N): 2 matoms x 8 natoms of m16n8k32.
__global__ __launch_bounds__(THREADS, 2)
void gemm_imma(const int8_t* __restrict__ qx, const int8_t* __restrict__ qw,
               const float* __restrict__ bias, float* __restrict__ out) {
    __shared__ __align__(1024) int8_t sA[STAGES][BM * BK];
    __shared__ __align__(1024) int8_t sB[STAGES][BN * BK];

    const int tid = threadIdx.x, wid = tid >> 5, lane = tid & 31;
    const int wM = wid & 3, wN = wid >> 2;
    const int row0 = blockIdx.y * BM;   // N_DIM
    const int col0 = blockIdx.x * BN;   // M_DIM

    const uint32_t sA0 = smem_u32(sA);
    const uint32_t sB0 = smem_u32(sB);

    const int8_t* aG = qx + (size_t)row0 * K_DIM;
    const int8_t* bG = qw + (size_t)col0 * K_DIM;

    int acc[2][8][4];
#pragma unroll
    for (int i = 0; i < 2; ++i)
#pragma unroll
        for (int j = 0; j < 8; ++j)
#pragma unroll
            for (int k = 0; k < 4; ++k) acc[i][j][k] = 0;

    // loader: per stage, A and B each 128 rows x 4 x 16B chunks = 512 chunks
    auto load_stage = [&](int s, int kt) {
        const int kb = kt * BK;
#pragma unroll
        for (int p = 0; p < 2; ++p) {
            int i = p * THREADS + tid;
            int r = i >> 2, c = i & 3;
            uint32_t so = swz((uint32_t)(r * BK + c * 16));
            cp16(sA0 + s * (BM * BK) + so, aG + (size_t)r * K_DIM + kb + c * 16);
            cp16(sB0 + s * (BN * BK) + so, bG + (size_t)r * K_DIM + kb + c * 16);
        }
        CP_COMMIT();
    };

    // ldmatrix address offsets (within a stage tile), per thread:
    // A (matom ma, katom kc): row = wM*32 + ma*16 + (lane&15), chunk = kc*2 + (lane>>4)
    uint32_t offA[2][2];
#pragma unroll
    for (int ma = 0; ma < 2; ++ma)
#pragma unroll
        for (int kc = 0; kc < 2; ++kc) {
            int r = wM * 32 + ma * 16 + (lane & 15);
            int ch = kc * 2 + (lane >> 4);
            offA[ma][kc] = swz((uint32_t)(r * BK + ch * 16));
        }
    // B (npair p, katom kc): col = wN*64 + p*16 + ((lane>>4)&1)*8 + (lane&7),
    //                        chunk = kc*2 + ((lane>>3)&1)
    uint32_t offB[4][2];
#pragma unroll
    for (int p = 0; p < 4; ++p)
#pragma unroll
        for (int kc = 0; kc < 2; ++kc) {
            int c = wN * 64 + p * 16 + ((lane >> 4) & 1) * 8 + (lane & 7);
            int ch = kc * 2 + ((lane >> 3) & 1);
            offB[p][kc] = swz((uint32_t)(c * BK + ch * 16));
        }

    // prologue
    load_stage(0, 0);
    load_stage(1, 1);

    for (int kt = 0; kt < K_TILES; ++kt) {
        const int s = kt % STAGES;
        if (kt + 2 < K_TILES) {
            asm volatile("cp.async.wait_group %0;" :: "n"(1) : "memory");
        } else {
            asm volatile("cp.async.wait_group %0;" :: "n"(0) : "memory");
        }
        __syncthreads();
        if (kt + 2 < K_TILES) load_stage((kt + 2) % STAGES, kt + 2);

        const uint32_t aBase = sA0 + s * (BM * BK);
        const uint32_t bBase = sB0 + s * (BN * BK);
#pragma unroll
        for (int kc = 0; kc < 2; ++kc) {
            uint32_t a[2][4];
            ldmx4(a[0], aBase + offA[0][kc]);
            ldmx4(a[1], aBase + offA[1][kc]);
#pragma unroll
            for (int p = 0; p < 4; ++p) {
                uint32_t b[4];   // {b0(2p), b1(2p), b0(2p+1), b1(2p+1)}
                ldmx4(b, bBase + offB[p][kc]);
                imma(acc[0][2 * p + 0], a[0], b[0], b[1]);
                imma(acc[1][2 * p + 0], a[1], b[0], b[1]);
                imma(acc[0][2 * p + 1], a[0], b[2], b[3]);
                imma(acc[1][2 * p + 1], a[1], b[2], b[3]);
            }
        }
    }

    // epilogue: dequant + bias
    const float dq = (__uint_as_float(g_amax_bits[0]) * __uint_as_float(g_amax_bits[1]))
                     / (127.0f * 127.0f);
    const int g = lane >> 2, tig = lane & 3;
    const int rbase = row0 + wM * 32;
    const int cbase = col0 + wN * 64;
#pragma unroll
    for (int ma = 0; ma < 2; ++ma) {
#pragma unroll
        for (int nb = 0; nb < 8; ++nb) {
            int r = rbase + ma * 16 + g;
            int c = cbase + nb * 8 + tig * 2;
            float2 bv = *(const float2*)(bias + c);
            float2 v0, v1;
            v0.x = (float)acc[ma][nb][0] * dq + bv.x;
            v0.y = (float)acc[ma][nb][1] * dq + bv.y;
            v1.x = (float)acc[ma][nb][2] * dq + bv.x;
            v1.y = (float)acc[ma][nb][3] * dq + bv.y;
            *(float2*)(out + (size_t)r * M_DIM + c) = v0;
            *(float2*)(out + (size_t)(r + 8) * M_DIM + c) = v1;
        }
    }
}

// ---------------------------------------------------------------- launch
extern "C" void kernel_launch(void* const* d_in, const int* in_sizes, int n_in,
                              void* d_out, int out_size) {
    const float* x = (const float*)d_in[0];
    const float* w = (const float*)d_in[1];
    const float* bias = (const float*)d_in[2];
    float* out = (float*)d_out;

    int8_t* qx;
    int8_t* qw;
    cudaGetSymbolAddress((void**)&qx, g_qx);
    cudaGetSymbolAddress((void**)&qw, g_qw);

    const long long nx4 = (long long)N_DIM * K_DIM / 4;
    const long long nw4 = (long long)M_DIM * K_DIM / 4;

    init_kernel<<<1, 32>>>();
    amax_kernel<<<1024, 256>>>(x, nx4, 0);
    amax_kernel<<<1024, 256>>>(w, nw4, 1);
    quant_kernel<<<1024, 256>>>(x, qx, nx4, 0);
    quant_kernel<<<1024, 256>>>(w, qw, nw4, 1);

    dim3 grid(M_DIM / BN, N_DIM / BM);
    gemm_imma<<<grid, THREADS>>>(qx, qw, bias, out);
}